// round 2
// baseline (speedup 1.0000x reference)
#include <cuda_runtime.h>
#include <cuda_bf16.h>
#include <mma.h>
using namespace nvcuda;

#define N_ROWS 4096
#define DIM    1024
#define VOCAB  32000
#define BM 128
#define BN 128
#define BK 32
#define LDA 40          // smem leading dim for bf16 tiles (pad 32 -> 40, mult of 8)
#define LDL 132         // smem leading dim for f32 logits tile (mult of 4)
#define SMEM_BYTES (BM * LDL * 4)   // 67584 bytes (union: > 2*BM*LDA*2 = 20480)

// ---- scratch (static device globals; allocation-free rule) ----
__device__ __nv_bfloat16 g_xb[N_ROWS * DIM];
__device__ __nv_bfloat16 g_wb[VOCAB * DIM];
__device__ float g_sumexp[N_ROWS];
__device__ float g_tgt[N_ROWS];
__device__ float g_sumlogit;
__device__ int   g_y[N_ROWS];
__device__ int   g_yflag;   // 1 => y is int32, 0 => y is int64

__global__ void zero_kernel() {
    int i = blockIdx.x * blockDim.x + threadIdx.x;
    if (i < N_ROWS) { g_sumexp[i] = 0.f; g_tgt[i] = 0.f; }
    if (i == 0) { g_sumlogit = 0.f; g_yflag = 0; }
}

// If y is int64 (little-endian), the odd 32-bit words of the first 4096 words
// are the high halves of labels < 32000 => all zero. If y is int32, the odd
// words are labels themselves; P(all 2048 are zero) ~ (1/32000)^2048 ~ 0.
__global__ void detect_y_kernel(const unsigned int* __restrict__ y) {
    int found = 0;
    for (int j = threadIdx.x; j < 2048; j += blockDim.x)
        if (y[2 * j + 1] != 0u) found = 1;
    int any = __syncthreads_or(found);
    if (threadIdx.x == 0) g_yflag = any;
}

__global__ void gather_y_kernel(const void* __restrict__ y) {
    int i = blockIdx.x * blockDim.x + threadIdx.x;
    if (i < N_ROWS) {
        g_y[i] = g_yflag ? ((const int*)y)[i]
                         : (int)(((const long long*)y)[i]);
    }
}

__global__ void convert_x_kernel(const float4* __restrict__ src) {
    __nv_bfloat162* dst = (__nv_bfloat162*)g_xb;
    int n4 = N_ROWS * DIM / 4;
    int stride = gridDim.x * blockDim.x;
    for (int i = blockIdx.x * blockDim.x + threadIdx.x; i < n4; i += stride) {
        float4 v = src[i];
        dst[2 * i]     = __floats2bfloat162_rn(v.x, v.y);
        dst[2 * i + 1] = __floats2bfloat162_rn(v.z, v.w);
    }
}

__global__ void convert_w_kernel(const float4* __restrict__ src) {
    __nv_bfloat162* dst = (__nv_bfloat162*)g_wb;
    int n4 = VOCAB * DIM / 4;
    int stride = gridDim.x * blockDim.x;
    for (int i = blockIdx.x * blockDim.x + threadIdx.x; i < n4; i += stride) {
        float4 v = src[i];
        dst[2 * i]     = __floats2bfloat162_rn(v.x, v.y);
        dst[2 * i + 1] = __floats2bfloat162_rn(v.z, v.w);
    }
}

// Fused GEMM (bf16 wmma) + per-tile softmax-statistics reduction.
// Grid: (VOCAB/BN, N_ROWS/BM). Block: 256 threads = 8 warps (4 along M, 2 along N).
__global__ void __launch_bounds__(256, 2) fused_kernel() {
    extern __shared__ char smem[];
    __nv_bfloat16* A_sh = (__nv_bfloat16*)smem;          // [BM][LDA]
    __nv_bfloat16* B_sh = A_sh + BM * LDA;               // [BN][LDA]
    float* L_sh = (float*)smem;                          // [BM][LDL] (reused after mainloop)

    const int v0 = blockIdx.x * BN;
    const int m0 = blockIdx.y * BM;
    const int tid = threadIdx.x;
    const int wid = tid >> 5, lane = tid & 31;
    const int wm = wid & 3;     // warp row   (4) -> 32 M-rows each
    const int wn = wid >> 2;    // warp col   (2) -> 64 N-cols each

    wmma::fragment<wmma::accumulator, 16, 16, 16, float> acc[2][4];
#pragma unroll
    for (int mi = 0; mi < 2; mi++)
#pragma unroll
        for (int ni = 0; ni < 4; ni++)
            wmma::fill_fragment(acc[mi][ni], 0.0f);

    for (int k0 = 0; k0 < DIM; k0 += BK) {
        // Stage A[128][32] and B[128][32] bf16 tiles (uint4 = 8 bf16 per load)
#pragma unroll
        for (int l = 0; l < 2; l++) {
            int idx = tid + (l << 8);
            int r = idx >> 2;
            int c = (idx & 3) << 3;
            *(uint4*)(A_sh + r * LDA + c) = *(const uint4*)(g_xb + (size_t)(m0 + r) * DIM + k0 + c);
            *(uint4*)(B_sh + r * LDA + c) = *(const uint4*)(g_wb + (size_t)(v0 + r) * DIM + k0 + c);
        }
        __syncthreads();

#pragma unroll
        for (int kk = 0; kk < BK; kk += 16) {
            wmma::fragment<wmma::matrix_a, 16, 16, 16, __nv_bfloat16, wmma::row_major> a[2];
#pragma unroll
            for (int mi = 0; mi < 2; mi++)
                wmma::load_matrix_sync(a[mi], A_sh + (wm * 32 + mi * 16) * LDA + kk, LDA);
#pragma unroll
            for (int ni = 0; ni < 4; ni++) {
                wmma::fragment<wmma::matrix_b, 16, 16, 16, __nv_bfloat16, wmma::col_major> b;
                wmma::load_matrix_sync(b, B_sh + (wn * 64 + ni * 16) * LDA + kk, LDA);
                wmma::mma_sync(acc[0][ni], a[0], b, acc[0][ni]);
                wmma::mma_sync(acc[1][ni], a[1], b, acc[1][ni]);
            }
        }
        __syncthreads();
    }

    // Spill the 128x128 logits tile to shared for row reductions
#pragma unroll
    for (int mi = 0; mi < 2; mi++)
#pragma unroll
        for (int ni = 0; ni < 4; ni++)
            wmma::store_matrix_sync(L_sh + (wm * 32 + mi * 16) * LDL + wn * 64 + ni * 16,
                                    acc[mi][ni], LDL, wmma::mem_row_major);
    __shared__ float bsl;
    if (tid == 0) bsl = 0.f;
    __syncthreads();

    // Two threads per row; each handles 64 columns.
    const int r = tid >> 1;
    const int half = tid & 1;
    const float* row = L_sh + r * LDL + (half << 6);
    float se = 0.f, sl = 0.f;
#pragma unroll 8
    for (int j = 0; j < 64; j++) {
        float v = row[j];
        se += __expf(v);
        sl += v;
    }
    float se_tot = se + __shfl_xor_sync(0xffffffffu, se, 1);
#pragma unroll
    for (int o = 16; o; o >>= 1) sl += __shfl_xor_sync(0xffffffffu, sl, o);
    if (lane == 0) atomicAdd(&bsl, sl);
    if (half == 0) atomicAdd(&g_sumexp[m0 + r], se_tot);

    int yv = g_y[m0 + r];
    int c = yv - v0 - (half << 6);
    if (c >= 0 && c < 64) g_tgt[m0 + r] = row[c];   // exactly one tile matches per row

    __syncthreads();
    if (tid == 0) atomicAdd(&g_sumlogit, bsl);
}

__global__ void finalize_kernel(float* __restrict__ out) {
    __shared__ float sa[32], sb[32];
    int tid = threadIdx.x;
    float a = 0.f, b = 0.f;
    for (int i = tid; i < N_ROWS; i += blockDim.x) {
        a += logf(g_sumexp[i]);    // lse (no max needed; logits are small)
        b += g_tgt[i];
    }
#pragma unroll
    for (int o = 16; o; o >>= 1) {
        a += __shfl_xor_sync(0xffffffffu, a, o);
        b += __shfl_xor_sync(0xffffffffu, b, o);
    }
    if ((tid & 31) == 0) { sa[tid >> 5] = a; sb[tid >> 5] = b; }
    __syncthreads();
    if (tid < 32) {
        a = sa[tid]; b = sb[tid];
#pragma unroll
        for (int o = 16; o; o >>= 1) {
            a += __shfl_xor_sync(0xffffffffu, a, o);
            b += __shfl_xor_sync(0xffffffffu, b, o);
        }
        if (tid == 0) {
            const float invN = 1.0f / (float)N_ROWS;
            float mean_lse = a * invN;
            float mean_tgt = b * invN;
            float loss = mean_lse - 0.9f * mean_tgt
                         - 0.1f * g_sumlogit / ((float)N_ROWS * (float)VOCAB);
            out[0] = loss;
        }
    }
}

extern "C" void kernel_launch(void* const* d_in, const int* in_sizes, int n_in,
                              void* d_out, int out_size) {
    const float* x = (const float*)d_in[0];
    const float* W = (const float*)d_in[1];
    const void*  y = d_in[2];
    float* out = (float*)d_out;

    (void)cudaFuncSetAttribute(fused_kernel, cudaFuncAttributeMaxDynamicSharedMemorySize, SMEM_BYTES);

    zero_kernel<<<(N_ROWS + 255) / 256, 256>>>();
    detect_y_kernel<<<1, 256>>>((const unsigned int*)y);
    gather_y_kernel<<<(N_ROWS + 255) / 256, 256>>>(y);
    convert_x_kernel<<<148 * 2, 256>>>((const float4*)x);
    convert_w_kernel<<<148 * 8, 256>>>((const float4*)W);

    dim3 grid(VOCAB / BN, N_ROWS / BM);   // 250 x 32 = 8000 CTAs
    fused_kernel<<<grid, 256, SMEM_BYTES>>>();

    finalize_kernel<<<1, 1024>>>(out);
}